// round 1
// baseline (speedup 1.0000x reference)
#include <cuda_runtime.h>
#include <cuda_bf16.h>
#include <math.h>

#define S_LEN 4096
#define HID   2048
#define NH    8
#define HD    256

// Scratch (device globals: no allocation allowed in kernel_launch)
__device__ float g_Q[(size_t)S_LEN * HID];          // 32 MB, [s, h*256+d]
__device__ float g_K[(size_t)S_LEN * HD];           // 4 MB,  [s, d]
__device__ float g_V[(size_t)S_LEN * HD];           // 4 MB,  [s, d]
__device__ float g_S[(size_t)NH * S_LEN * S_LEN];   // 512 MB, [h, q, k]
__device__ float g_A[(size_t)S_LEN * HID];          // 32 MB, [s, h*256+d]

// ---------------------------------------------------------------------------
// Generic batched SGEMM: C = alpha * A @ B(^T)
// 128x128 CTA tile, 8x8 per thread, BK=8, 256 threads.
// A: [M,K] row-major, lda. B: NN -> [K,N] ldb ; NT -> [N,K] ldb. C: [M,N] ldc.
// blockIdx.z batches with per-matrix strides.
// All dims assumed multiples of tile sizes (true for this problem).
// ---------------------------------------------------------------------------
template <bool TRANSB>
__global__ void __launch_bounds__(256) sgemm_kernel(
    const float* __restrict__ A, const float* __restrict__ B,
    float* __restrict__ C,
    int M, int N, int K, int lda, int ldb, int ldc,
    long long strideA, long long strideB, long long strideC, float alpha)
{
    const int z = blockIdx.z;
    A += (long long)z * strideA;
    B += (long long)z * strideB;
    C += (long long)z * strideC;

    const int m0 = blockIdx.y * 128;
    const int n0 = blockIdx.x * 128;
    const int tid = threadIdx.x;
    const int tx = tid & 15;   // 0..15 -> col group
    const int ty = tid >> 4;   // 0..15 -> row group

    __shared__ float As[8][128];
    __shared__ float Bs[8][128];

    float acc[8][8];
#pragma unroll
    for (int i = 0; i < 8; i++)
#pragma unroll
        for (int j = 0; j < 8; j++) acc[i][j] = 0.0f;

    for (int k0 = 0; k0 < K; k0 += 8) {
        // --- load A tile: 128 rows x 8 k, transposed into As[k][row]
        {
            const int row = tid >> 1;
            const int kg  = (tid & 1) * 4;
            const float4 av = *(const float4*)&A[(long long)(m0 + row) * lda + k0 + kg];
            As[kg + 0][row] = av.x;
            As[kg + 1][row] = av.y;
            As[kg + 2][row] = av.z;
            As[kg + 3][row] = av.w;
        }
        // --- load B tile into Bs[k][col]
        if (TRANSB) {
            const int col = tid >> 1;
            const int kg  = (tid & 1) * 4;
            const float4 bv = *(const float4*)&B[(long long)(n0 + col) * ldb + k0 + kg];
            Bs[kg + 0][col] = bv.x;
            Bs[kg + 1][col] = bv.y;
            Bs[kg + 2][col] = bv.z;
            Bs[kg + 3][col] = bv.w;
        } else {
            const int kk = tid >> 5;          // 0..7
            const int c4 = (tid & 31) * 4;    // 0..124
            const float4 bv = *(const float4*)&B[(long long)(k0 + kk) * ldb + n0 + c4];
            *(float4*)&Bs[kk][c4] = bv;
        }
        __syncthreads();

#pragma unroll
        for (int kk = 0; kk < 8; kk++) {
            float a[8], b[8];
            const float4 a0 = *(const float4*)&As[kk][ty * 8];
            const float4 a1 = *(const float4*)&As[kk][ty * 8 + 4];
            const float4 b0 = *(const float4*)&Bs[kk][tx * 8];
            const float4 b1 = *(const float4*)&Bs[kk][tx * 8 + 4];
            a[0]=a0.x; a[1]=a0.y; a[2]=a0.z; a[3]=a0.w;
            a[4]=a1.x; a[5]=a1.y; a[6]=a1.z; a[7]=a1.w;
            b[0]=b0.x; b[1]=b0.y; b[2]=b0.z; b[3]=b0.w;
            b[4]=b1.x; b[5]=b1.y; b[6]=b1.z; b[7]=b1.w;
#pragma unroll
            for (int i = 0; i < 8; i++)
#pragma unroll
                for (int j = 0; j < 8; j++)
                    acc[i][j] = fmaf(a[i], b[j], acc[i][j]);
        }
        __syncthreads();
    }

    // --- write C
#pragma unroll
    for (int i = 0; i < 8; i++) {
        float* crow = &C[(long long)(m0 + ty * 8 + i) * ldc + n0 + tx * 8];
        float4 c0, c1;
        c0.x = acc[i][0] * alpha; c0.y = acc[i][1] * alpha;
        c0.z = acc[i][2] * alpha; c0.w = acc[i][3] * alpha;
        c1.x = acc[i][4] * alpha; c1.y = acc[i][5] * alpha;
        c1.z = acc[i][6] * alpha; c1.w = acc[i][7] * alpha;
        *(float4*)&crow[0] = c0;
        *(float4*)&crow[4] = c1;
    }
}

// ---------------------------------------------------------------------------
// RoPE in-place on g_Q (8 heads) and g_K (1 head).
// grid = S_LEN blocks, 128 threads (one per rotation pair index j).
// out[j]     = x1*cos - x2*sin
// out[j+128] = x2*cos + x1*sin       (cos/sin identical for j and j+128)
// ---------------------------------------------------------------------------
__global__ void rope_kernel(const int* __restrict__ pos_ids)
{
    const int s = blockIdx.x;
    const int j = threadIdx.x;           // 0..127
    const float p = (float)pos_ids[s];
    const float inv = expf(-((float)j * (1.0f / 128.0f)) * logf(10000.0f));
    const float ang = p * inv;
    const float c  = cosf(ang);
    const float sn = sinf(ang);

#pragma unroll
    for (int h = 0; h < NH; h++) {
        float* q = g_Q + (size_t)s * HID + h * HD;
        const float x1 = q[j];
        const float x2 = q[j + 128];
        q[j]       = x1 * c - x2 * sn;
        q[j + 128] = x2 * c + x1 * sn;
    }
    float* k = g_K + (size_t)s * HD;
    const float x1 = k[j];
    const float x2 = k[j + 128];
    k[j]       = x1 * c - x2 * sn;
    k[j + 128] = x2 * c + x1 * sn;
}

// ---------------------------------------------------------------------------
// Row softmax over g_S[h][q][:], adding attention_mask[q][:] (already scaled
// scores: alpha=1/16 applied in the QK^T GEMM).
// grid = (S_LEN, NH), 256 threads.
// ---------------------------------------------------------------------------
__global__ void softmax_kernel(const float* __restrict__ mask)
{
    const int q = blockIdx.x;
    const int h = blockIdx.y;
    float* __restrict__ row = g_S + ((size_t)h * S_LEN + q) * S_LEN;
    const float* __restrict__ mrow = mask + (size_t)q * S_LEN;
    const int tid = threadIdx.x;

    __shared__ float red[256];

    float m = -1e30f;
    for (int k = tid; k < S_LEN; k += 256) {
        const float v = row[k] + mrow[k];
        m = fmaxf(m, v);
    }
    red[tid] = m;
    __syncthreads();
    for (int st = 128; st > 0; st >>= 1) {
        if (tid < st) red[tid] = fmaxf(red[tid], red[tid + st]);
        __syncthreads();
    }
    m = red[0];
    __syncthreads();

    float sum = 0.0f;
    for (int k = tid; k < S_LEN; k += 256) {
        const float v = expf(row[k] + mrow[k] - m);
        row[k] = v;
        sum += v;
    }
    red[tid] = sum;
    __syncthreads();
    for (int st = 128; st > 0; st >>= 1) {
        if (tid < st) red[tid] += red[tid + st];
        __syncthreads();
    }
    const float inv = 1.0f / red[0];
    for (int k = tid; k < S_LEN; k += 256) row[k] *= inv;
}

// ---------------------------------------------------------------------------
// Launch
// inputs: 0 hidden_states f32 [1,4096,2048], 1 attention_mask f32 [1,1,4096,4096],
//         2 position_ids i32 [1,4096], 3 Wq [2048,2048], 4 Wk [2048,256],
//         5 Wv [2048,256], 6 Wo [2048,2048]. output f32 [1,4096,2048].
// ---------------------------------------------------------------------------
extern "C" void kernel_launch(void* const* d_in, const int* in_sizes, int n_in,
                              void* d_out, int out_size)
{
    const float* X    = (const float*)d_in[0];
    const float* mask = (const float*)d_in[1];
    const int*   pos  = (const int*)d_in[2];
    const float* Wq   = (const float*)d_in[3];
    const float* Wk   = (const float*)d_in[4];
    const float* Wv   = (const float*)d_in[5];
    const float* Wo   = (const float*)d_in[6];
    float* out = (float*)d_out;

    float *Q, *K, *V, *Sb, *A;
    cudaGetSymbolAddress((void**)&Q,  g_Q);
    cudaGetSymbolAddress((void**)&K,  g_K);
    cudaGetSymbolAddress((void**)&V,  g_V);
    cudaGetSymbolAddress((void**)&Sb, g_S);
    cudaGetSymbolAddress((void**)&A,  g_A);

    const dim3 blk(256);

    // Q = X @ Wq    [4096,2048]
    sgemm_kernel<false><<<dim3(HID / 128, S_LEN / 128, 1), blk>>>(
        X, Wq, Q, S_LEN, HID, HID, HID, HID, HID, 0, 0, 0, 1.0f);
    // K = X @ Wk    [4096,256]
    sgemm_kernel<false><<<dim3(HD / 128, S_LEN / 128, 1), blk>>>(
        X, Wk, K, S_LEN, HD, HID, HID, HD, HD, 0, 0, 0, 1.0f);
    // V = X @ Wv    [4096,256]
    sgemm_kernel<false><<<dim3(HD / 128, S_LEN / 128, 1), blk>>>(
        X, Wv, V, S_LEN, HD, HID, HID, HD, HD, 0, 0, 0, 1.0f);

    // RoPE in-place on Q, K
    rope_kernel<<<S_LEN, 128>>>(pos);

    // scores[h] = (Q_h @ K^T) / 16     batched over 8 heads (NT GEMM)
    sgemm_kernel<true><<<dim3(S_LEN / 128, S_LEN / 128, NH), blk>>>(
        Q, K, Sb, S_LEN, S_LEN, HD,
        HID, HD, S_LEN,
        (long long)HD, 0, (long long)S_LEN * S_LEN, 1.0f / 16.0f);

    // softmax(scores + mask) row-wise
    softmax_kernel<<<dim3(S_LEN, NH), 256>>>(mask);

    // A[:, h*256:(h+1)*256] = P_h @ V   batched (NN GEMM)
    sgemm_kernel<false><<<dim3(HD / 128, S_LEN / 128, NH), blk>>>(
        Sb, V, A, S_LEN, HD, S_LEN,
        S_LEN, HD, HID,
        (long long)S_LEN * S_LEN, 0, (long long)HD, 1.0f);

    // out = A @ Wo
    sgemm_kernel<false><<<dim3(HID / 128, S_LEN / 128, 1), blk>>>(
        A, Wo, out, S_LEN, HID, HID, HID, HID, HID, 0, 0, 0, 1.0f);
}

// round 3
// speedup vs baseline: 2.8161x; 2.8161x over previous
#include <cuda_runtime.h>
#include <cuda_bf16.h>
#include <math.h>
#include <cstdint>

#define S_LEN 4096
#define HID   2048
#define NH    8
#define HD    256

// ------------------------- device scratch (no allocs allowed) ---------------
__device__ float g_Q  [(size_t)S_LEN * HID];          // 32 MB  [s, h*256+d]
__device__ float g_K  [(size_t)S_LEN * HD];           // 4 MB   [s, d]
__device__ float g_V  [(size_t)S_LEN * HD];           // 4 MB   [s, d]
__device__ float g_VT [(size_t)HD * S_LEN];           // 4 MB   [d, s]
__device__ float g_S  [(size_t)NH * S_LEN * S_LEN];   // 512 MB [h, q, k]
__device__ float g_A  [(size_t)S_LEN * HID];          // 32 MB  [s, h*256+d]
__device__ float g_WqT[(size_t)HID * HID];            // 16 MB  [n, k]
__device__ float g_WkT[(size_t)HD * HID];             // 2 MB
__device__ float g_WvT[(size_t)HD * HID];             // 2 MB
__device__ float g_WoT[(size_t)HID * HID];            // 16 MB

// ---------------------------------------------------------------------------
// tf32 tensor-core GEMM (NT form): C[m,n] = alpha * sum_k A[m,k] * B[n,k]
// CTA tile 128x128, K-chunk 32, 256 threads (8 warps, 2x4 warp grid,
// warp tile 64x32 via m16n8k8 mma.sync). Batched over blockIdx.z.
// M,N multiples of 128; K multiple of 32.
// SMEM tiles [128][36] row-major (pad 32->36): conflict-free fragment LDS.
// ---------------------------------------------------------------------------
#define TLD 36

__device__ __forceinline__ uint32_t f2tf32(float x) {
    uint32_t r;
    asm("cvt.rna.tf32.f32 %0, %1;" : "=r"(r) : "f"(x));
    return r;
}

__global__ void __launch_bounds__(256, 2) tgemm_tf32(
    const float* __restrict__ A, const float* __restrict__ B, float* __restrict__ C,
    int K, int lda, int ldb, int ldc,
    long long sA, long long sB, long long sC, float alpha)
{
    __shared__ float As[128 * TLD];
    __shared__ float Bs[128 * TLD];

    const int tid  = threadIdx.x;
    const int wid  = tid >> 5;
    const int lane = tid & 31;
    const int g    = lane >> 2;    // 0..7
    const int tg   = lane & 3;     // 0..3
    const int wm   = (wid >> 2) * 64;   // warp m offset in CTA tile
    const int wn   = (wid & 3) * 32;    // warp n offset

    const int z = blockIdx.z;
    const int m0 = blockIdx.y * 128;
    const int n0 = blockIdx.x * 128;
    A += (long long)z * sA + (long long)m0 * lda;
    B += (long long)z * sB + (long long)n0 * ldb;
    C += (long long)z * sC;

    float acc[4][4][4];
#pragma unroll
    for (int i = 0; i < 4; i++)
#pragma unroll
        for (int j = 0; j < 4; j++)
#pragma unroll
            for (int r = 0; r < 4; r++) acc[i][j][r] = 0.0f;

    for (int k0 = 0; k0 < K; k0 += 32) {
        // ---- fill SMEM tiles (coalesced float4 loads, tf32-converted) ----
#pragma unroll
        for (int i = 0; i < 4; i++) {
            const int f  = i * 256 + tid;        // 0..1023
            const int m  = f >> 3;               // 0..127
            const int c4 = (f & 7) << 2;         // 0,4,...,28
            const float4 av = *(const float4*)(A + (long long)m * lda + k0 + c4);
            uint4 at;
            at.x = f2tf32(av.x); at.y = f2tf32(av.y);
            at.z = f2tf32(av.z); at.w = f2tf32(av.w);
            *(uint4*)(As + m * TLD + c4) = at;
            const float4 bv = *(const float4*)(B + (long long)m * ldb + k0 + c4);
            uint4 bt;
            bt.x = f2tf32(bv.x); bt.y = f2tf32(bv.y);
            bt.z = f2tf32(bv.z); bt.w = f2tf32(bv.w);
            *(uint4*)(Bs + m * TLD + c4) = bt;
        }
        __syncthreads();

        // ---- compute: 4 k-steps of 8 ----
#pragma unroll
        for (int ks = 0; ks < 4; ks++) {
            uint32_t af[4][4];
            uint32_t bf[4][2];
#pragma unroll
            for (int tm = 0; tm < 4; tm++) {
                const float* p = As + (wm + tm * 16 + g) * TLD + ks * 8 + tg;
                af[tm][0] = __float_as_uint(p[0]);
                af[tm][1] = __float_as_uint(p[8 * TLD]);
                af[tm][2] = __float_as_uint(p[4]);
                af[tm][3] = __float_as_uint(p[8 * TLD + 4]);
            }
#pragma unroll
            for (int tn = 0; tn < 4; tn++) {
                const float* p = Bs + (wn + tn * 8 + g) * TLD + ks * 8 + tg;
                bf[tn][0] = __float_as_uint(p[0]);
                bf[tn][1] = __float_as_uint(p[4]);
            }
#pragma unroll
            for (int tm = 0; tm < 4; tm++)
#pragma unroll
                for (int tn = 0; tn < 4; tn++) {
                    asm volatile(
                        "mma.sync.aligned.m16n8k8.row.col.f32.tf32.tf32.f32 "
                        "{%0,%1,%2,%3}, {%4,%5,%6,%7}, {%8,%9}, {%0,%1,%2,%3};"
                        : "+f"(acc[tm][tn][0]), "+f"(acc[tm][tn][1]),
                          "+f"(acc[tm][tn][2]), "+f"(acc[tm][tn][3])
                        : "r"(af[tm][0]), "r"(af[tm][1]),
                          "r"(af[tm][2]), "r"(af[tm][3]),
                          "r"(bf[tn][0]), "r"(bf[tn][1]));
                }
        }
        __syncthreads();
    }

    // ---- epilogue ----
#pragma unroll
    for (int tm = 0; tm < 4; tm++) {
        const int row = m0 + wm + tm * 16 + g;
#pragma unroll
        for (int tn = 0; tn < 4; tn++) {
            const int col = n0 + wn + tn * 8 + 2 * tg;
            float2 lo, hi;
            lo.x = acc[tm][tn][0] * alpha; lo.y = acc[tm][tn][1] * alpha;
            hi.x = acc[tm][tn][2] * alpha; hi.y = acc[tm][tn][3] * alpha;
            *(float2*)(C + (long long)row * ldc + col) = lo;
            *(float2*)(C + (long long)(row + 8) * ldc + col) = hi;
        }
    }
}

// ---------------------------------------------------------------------------
// Transpose: out[c][r] = in[r][c], R,C multiples of 32. grid (C/32, R/32).
// ---------------------------------------------------------------------------
__global__ void __launch_bounds__(256) transpose_kernel(
    const float* __restrict__ in, float* __restrict__ out, int R, int C)
{
    __shared__ float tile[32][33];
    const int c0 = blockIdx.x * 32;
    const int r0 = blockIdx.y * 32;
    const int x = threadIdx.x;   // 0..31
    const int y = threadIdx.y;   // 0..7
#pragma unroll
    for (int i = 0; i < 32; i += 8)
        tile[y + i][x] = in[(long long)(r0 + y + i) * C + c0 + x];
    __syncthreads();
#pragma unroll
    for (int i = 0; i < 32; i += 8)
        out[(long long)(c0 + y + i) * R + r0 + x] = tile[x][y + i];
}

// ---------------------------------------------------------------------------
// RoPE in-place on g_Q (8 heads) and g_K.
// ---------------------------------------------------------------------------
__global__ void rope_kernel(const int* __restrict__ pos_ids)
{
    const int s = blockIdx.x;
    const int j = threadIdx.x;           // 0..127
    const float p = (float)pos_ids[s];
    const float inv = expf(-((float)j * (1.0f / 128.0f)) * logf(10000.0f));
    const float ang = p * inv;
    const float c  = cosf(ang);
    const float sn = sinf(ang);

#pragma unroll
    for (int h = 0; h < NH; h++) {
        float* q = g_Q + (size_t)s * HID + h * HD;
        const float x1 = q[j];
        const float x2 = q[j + 128];
        q[j]       = x1 * c - x2 * sn;
        q[j + 128] = x2 * c + x1 * sn;
    }
    float* k = g_K + (size_t)s * HD;
    const float x1 = k[j];
    const float x2 = k[j + 128];
    k[j]       = x1 * c - x2 * sn;
    k[j + 128] = x2 * c + x1 * sn;
}

// ---------------------------------------------------------------------------
// Single-pass softmax over g_S[h][q][:] with mask add. 16 elems/thread in regs.
// grid = (S_LEN, NH), 256 threads.
// ---------------------------------------------------------------------------
__global__ void __launch_bounds__(256) softmax_kernel(const float* __restrict__ mask)
{
    const int q = blockIdx.x;
    const int h = blockIdx.y;
    float* __restrict__ row = g_S + ((size_t)h * S_LEN + q) * S_LEN;
    const float* __restrict__ mrow = mask + (size_t)q * S_LEN;
    const int tid = threadIdx.x;

    float v[16];
    float m = -1e30f;
#pragma unroll
    for (int i = 0; i < 16; i++) {
        const int k = tid + i * 256;
        v[i] = row[k] + mrow[k];
        m = fmaxf(m, v[i]);
    }

    __shared__ float red[256];
    red[tid] = m;
    __syncthreads();
    for (int st = 128; st > 0; st >>= 1) {
        if (tid < st) red[tid] = fmaxf(red[tid], red[tid + st]);
        __syncthreads();
    }
    m = red[0];
    __syncthreads();

    float sum = 0.0f;
#pragma unroll
    for (int i = 0; i < 16; i++) {
        v[i] = __expf(v[i] - m);
        sum += v[i];
    }
    red[tid] = sum;
    __syncthreads();
    for (int st = 128; st > 0; st >>= 1) {
        if (tid < st) red[tid] += red[tid + st];
        __syncthreads();
    }
    const float inv = 1.0f / red[0];
#pragma unroll
    for (int i = 0; i < 16; i++) row[tid + i * 256] = v[i] * inv;
}

// ---------------------------------------------------------------------------
// Launch
// ---------------------------------------------------------------------------
extern "C" void kernel_launch(void* const* d_in, const int* in_sizes, int n_in,
                              void* d_out, int out_size)
{
    const float* X    = (const float*)d_in[0];
    const float* mask = (const float*)d_in[1];
    const int*   pos  = (const int*)d_in[2];
    const float* Wq   = (const float*)d_in[3];
    const float* Wk   = (const float*)d_in[4];
    const float* Wv   = (const float*)d_in[5];
    const float* Wo   = (const float*)d_in[6];
    float* out = (float*)d_out;

    float *Q, *K, *V, *VT, *Sb, *A, *WqT, *WkT, *WvT, *WoT;
    cudaGetSymbolAddress((void**)&Q,   g_Q);
    cudaGetSymbolAddress((void**)&K,   g_K);
    cudaGetSymbolAddress((void**)&V,   g_V);
    cudaGetSymbolAddress((void**)&VT,  g_VT);
    cudaGetSymbolAddress((void**)&Sb,  g_S);
    cudaGetSymbolAddress((void**)&A,   g_A);
    cudaGetSymbolAddress((void**)&WqT, g_WqT);
    cudaGetSymbolAddress((void**)&WkT, g_WkT);
    cudaGetSymbolAddress((void**)&WvT, g_WvT);
    cudaGetSymbolAddress((void**)&WoT, g_WoT);

    const dim3 tb(32, 8);
    // weight transposes ([K,N] -> [N,K])
    transpose_kernel<<<dim3(HID / 32, HID / 32), tb>>>(Wq, WqT, HID, HID);
    transpose_kernel<<<dim3(HD  / 32, HID / 32), tb>>>(Wk, WkT, HID, HD);
    transpose_kernel<<<dim3(HD  / 32, HID / 32), tb>>>(Wv, WvT, HID, HD);
    transpose_kernel<<<dim3(HID / 32, HID / 32), tb>>>(Wo, WoT, HID, HID);

    // projections
    tgemm_tf32<<<dim3(HID / 128, S_LEN / 128, 1), 256>>>(
        X, WqT, Q, HID, HID, HID, HID, 0, 0, 0, 1.0f);
    tgemm_tf32<<<dim3(HD / 128, S_LEN / 128, 1), 256>>>(
        X, WkT, K, HID, HID, HID, HD, 0, 0, 0, 1.0f);
    tgemm_tf32<<<dim3(HD / 128, S_LEN / 128, 1), 256>>>(
        X, WvT, V, HID, HID, HID, HD, 0, 0, 0, 1.0f);

    // RoPE on Q, K
    rope_kernel<<<S_LEN, 128>>>(pos);

    // V^T for the PV GEMM
    transpose_kernel<<<dim3(HD / 32, S_LEN / 32), tb>>>(V, VT, S_LEN, HD);

    // scores[h] = (Q_h @ K^T) / 16
    tgemm_tf32<<<dim3(S_LEN / 128, S_LEN / 128, NH), 256>>>(
        Q, K, Sb, HD, HID, HD, S_LEN,
        (long long)HD, 0, (long long)S_LEN * S_LEN, 1.0f / 16.0f);

    // softmax(scores + mask)
    softmax_kernel<<<dim3(S_LEN, NH), 256>>>(mask);

    // A[:, h*256:(h+1)*256] = P_h @ V   (B = V^T, NT form)
    tgemm_tf32<<<dim3(HD / 128, S_LEN / 128, NH), 256>>>(
        Sb, VT, A, S_LEN, S_LEN, S_LEN, HID,
        (long long)S_LEN * S_LEN, 0, (long long)HD, 1.0f);

    // out = A @ Wo
    tgemm_tf32<<<dim3(HID / 128, S_LEN / 128, 1), 256>>>(
        A, WoT, out, HID, HID, HID, HID, 0, 0, 0, 1.0f);
}